// round 15
// baseline (speedup 1.0000x reference)
#include <cuda_runtime.h>
#include <cstdint>
#include <float.h>
#include <math.h>

// ---------------------------------------------------------------------------
// TS2Vec hierarchical loss, B=8, T=2048, C=64, ALPHA=0.5, TAU=0.1, EPS=1e-5
// Round 15: k_temp chunked — one block per (l,b,256-row chunk) streams norms/
// col-sums into per-(l,b) global accumulators; last chunk block runs the
// candidate-pair + closed-form finish. Heaviest block: 64KB (was 512KB).
// ---------------------------------------------------------------------------

#define TTOP 2048
#define CDIM 64
#define NLB  176                                   // 11 levels * 16 b

__device__ double g_acc;
__device__ int g_ctr;                              // finisher completion
__device__ __align__(16) float g_pyr[2][8 * 2047 * 64];
__device__ float g_norm[4094 * 16];                // per-row |z|^2
__device__ float g_svec[NLB * 64];                 // per-(l,b) column sums
__device__ double g_nrm[NLB];                      // per-(l,b) sum of norms
__device__ int g_mx[NLB];                          // per-(l,b) max norm (bits)
__device__ int g_ctr2[NLB];                        // per-(l,b) chunk counter

__device__ __forceinline__ int pyrOff(int l) { return 512 * (2048 - (4096 >> l)); }
__device__ __forceinline__ int rowOff(int l) { return 4096 - (4096 >> l); }
__device__ __forceinline__ const float* lvl_base(int l, int b,
                                                 const float* z1, const float* z2) {
    int bb = b & 7;
    const float* z = (b < 8) ? z1 : z2;
    const float* p = (b < 8) ? g_pyr[0] : g_pyr[1];
    if (l == 0) return z + (size_t)bb * TTOP * CDIM;
    return p + pyrOff(l) + (size_t)bb * (size_t)(TTOP >> l) * CDIM;
}
__device__ __forceinline__ int chunksOf(int l) {
    int T = TTOP >> l;
    return (T + 255) >> 8;                         // 8,4,2,1,1,...
}

__device__ __forceinline__ float tf32r(float x) {
    uint32_t r;
    asm("cvt.rna.tf32.f32 %0, %1;" : "=r"(r) : "f"(x));
    return __uint_as_float(r);
}
__device__ __forceinline__ float4 tf32r4(float4 v) {
    return make_float4(tf32r(v.x), tf32r(v.y), tf32r(v.z), tf32r(v.w));
}

__device__ __forceinline__ void mma_tf32(float c[4], uint32_t a0, uint32_t a1,
                                         uint32_t a2, uint32_t a3,
                                         uint32_t b0, uint32_t b1) {
    asm volatile(
        "mma.sync.aligned.m16n8k8.row.col.f32.tf32.tf32.f32 "
        "{%0,%1,%2,%3}, {%4,%5,%6,%7}, {%8,%9}, {%0,%1,%2,%3};"
        : "+f"(c[0]), "+f"(c[1]), "+f"(c[2]), "+f"(c[3])
        : "r"(a0), "r"(a1), "r"(a2), "r"(a3), "r"(b0), "r"(b1));
}

// ---------------------------------------------------------------------------
// Pool levels 1..6 in ONE pass (binary max tree). Also zeroes accumulators.
__global__ void __launch_bounds__(256)
k_poolA(const float* __restrict__ z1, const float* __restrict__ z2) {
    int idx = blockIdx.x * 256 + threadIdx.x;       // 0..32767
    if (idx == 0) { g_acc = 0.0; g_ctr = 0; }
    if (idx < NLB * 64) g_svec[idx] = 0.f;
    if (idx < NLB) { g_nrm[idx] = 0.0; g_mx[idx] = 0; g_ctr2[idx] = 0; }
    int c = idx & 63;
    int seg = (idx >> 6) & 31;
    int b = (idx >> 11) & 7;
    int tensor = idx >> 14;
    const float* in = tensor ? z2 : z1;
    const float* base = in + ((size_t)b * TTOP + seg * 64) * CDIM + c;
    float* pyr = g_pyr[tensor];

    float c1 = 0.f, c2 = 0.f, c3 = 0.f, c4 = 0.f, c5 = 0.f;
#pragma unroll
    for (int i = 0; i < 32; i++) {
        float a0 = base[(size_t)(2 * i) * CDIM];
        float a1 = base[(size_t)(2 * i + 1) * CDIM];
        float m1 = fmaxf(a0, a1);
        pyr[pyrOff(1) + ((size_t)b * 1024 + seg * 32 + i) * CDIM + c] = m1;
        if (i & 1) {
            float m2 = fmaxf(c1, m1);
            pyr[pyrOff(2) + ((size_t)b * 512 + seg * 16 + (i >> 1)) * CDIM + c] = m2;
            if (i & 2) {
                float m3 = fmaxf(c2, m2);
                pyr[pyrOff(3) + ((size_t)b * 256 + seg * 8 + (i >> 2)) * CDIM + c] = m3;
                if (i & 4) {
                    float m4 = fmaxf(c3, m3);
                    pyr[pyrOff(4) + ((size_t)b * 128 + seg * 4 + (i >> 3)) * CDIM + c] = m4;
                    if (i & 8) {
                        float m5 = fmaxf(c4, m4);
                        pyr[pyrOff(5) + ((size_t)b * 64 + seg * 2 + (i >> 4)) * CDIM + c] = m5;
                        if (i & 16) {
                            float m6 = fmaxf(c5, m5);
                            pyr[pyrOff(6) + ((size_t)b * 32 + seg) * CDIM + c] = m6;
                        } else c5 = m5;
                    } else c4 = m4;
                } else c3 = m3;
            } else c2 = m2;
        } else c1 = m1;
    }
}

// Pool levels 7..11 from level 6 (T6 = 32).
__global__ void k_poolB() {
    int idx = blockIdx.x * blockDim.x + threadIdx.x;
    const int NPER = 512 * 31;
    if (idx >= 2 * NPER) return;
    int tensor = (idx >= NPER) ? 1 : 0;
    int off = idx - tensor * NPER;
    int l = 7, T = 16;
    while (off >= 512 * T) { off -= 512 * T; ++l; T >>= 1; }
    int c = off & 63;
    int t = (off >> 6) % T;
    int b = (off >> 6) / T;
    int w = 32 / T;
    const float* src = g_pyr[tensor] + pyrOff(6) + ((size_t)b * 32 + (size_t)t * w) * CDIM + c;
    float m = src[0];
    for (int k = 1; k < w; k++) m = fmaxf(m, src[(size_t)k * CDIM]);
    g_pyr[tensor][pyrOff(l) + ((size_t)b * T + t) * CDIM + c] = m;
}

// ---------------------------------------------------------------------------
// Instance loss via tf32 mma: one warp per slice, 8 warps/block.
__global__ void __launch_bounds__(256)
k_inst(const float* __restrict__ z1, const float* __restrict__ z2) {
    __shared__ float4 apack[8][8 * 36];
    __shared__ double wres[8];
    int tid = threadIdx.x;
    int w = tid >> 5, lid = tid & 31;
    int gq = lid >> 2, t4 = lid & 3;
    int slice = blockIdx.x * 8 + w;
    double myres = 0.0;

    if (slice < 4095) {
        int l = 0, T = TTOP, tt = slice;
        while (tt >= T) { tt -= T; ++l; T >>= 1; }

#pragma unroll
        for (int i = 0; i < 2; i++) {
            int task = lid + 32 * i;
            int rp = task >> 3, s = task & 7;
            const float* pa = lvl_base(l, rp, z1, z2) + (size_t)tt * CDIM + 8 * s;
            const float* pb = lvl_base(l, rp + 8, z1, z2) + (size_t)tt * CDIM + 8 * s;
            float4 u0 = tf32r4(*reinterpret_cast<const float4*>(pa));
            float4 u1 = tf32r4(*reinterpret_cast<const float4*>(pa + 4));
            float4 v0 = tf32r4(*reinterpret_cast<const float4*>(pb));
            float4 v1 = tf32r4(*reinterpret_cast<const float4*>(pb + 4));
            float4* ap = &apack[w][rp * 36 + s * 4];
            ap[0] = make_float4(u0.x, v0.x, u1.x, v1.x);
            ap[1] = make_float4(u0.y, v0.y, u1.y, v1.y);
            ap[2] = make_float4(u0.z, v0.z, u1.z, v1.z);
            ap[3] = make_float4(u0.w, v0.w, u1.w, v1.w);
        }
        __syncwarp();

        float acc0[4] = {0.f, 0.f, 0.f, 0.f};
        float acc1[4] = {0.f, 0.f, 0.f, 0.f};
#pragma unroll
        for (int s = 0; s < 8; s++) {
            float4 a = apack[w][gq * 36 + s * 4 + t4];
            uint32_t ax = __float_as_uint(a.x), ay = __float_as_uint(a.y);
            uint32_t az = __float_as_uint(a.z), aw = __float_as_uint(a.w);
            mma_tf32(acc0, ax, ay, az, aw, ax, az);
            mma_tf32(acc1, ax, ay, az, aw, ay, aw);
        }

        int j0 = 2 * t4, j1 = 2 * t4 + 1;
        float vA0 = (j0 == gq) ? -FLT_MAX : acc0[0];
        float vA1 = (j1 == gq) ? -FLT_MAX : acc0[1];
        float vA2 = acc1[0], vA3 = acc1[1];
        float vB0 = acc0[2], vB1 = acc0[3];
        float vB2 = (j0 == gq) ? -FLT_MAX : acc1[2];
        float vB3 = (j1 == gq) ? -FLT_MAX : acc1[3];

        float mA = fmaxf(fmaxf(vA0, vA1), fmaxf(vA2, vA3));
        float mB = fmaxf(fmaxf(vB0, vB1), fmaxf(vB2, vB3));
        mA = fmaxf(mA, __shfl_xor_sync(0xffffffffu, mA, 1));
        mA = fmaxf(mA, __shfl_xor_sync(0xffffffffu, mA, 2));
        mB = fmaxf(mB, __shfl_xor_sync(0xffffffffu, mB, 1));
        mB = fmaxf(mB, __shfl_xor_sync(0xffffffffu, mB, 2));

        float eA = __expf(vA0 - mA) + __expf(vA1 - mA) +
                   __expf(vA2 - mA) + __expf(vA3 - mA);
        float eB = __expf(vB0 - mB) + __expf(vB1 - mB) +
                   __expf(vB2 - mB) + __expf(vB3 - mB);
        eA += __shfl_xor_sync(0xffffffffu, eA, 1);
        eA += __shfl_xor_sync(0xffffffffu, eA, 2);
        eB += __shfl_xor_sync(0xffffffffu, eB, 1);
        eB += __shfl_xor_sync(0xffffffffu, eB, 2);

        float pA = ((j0 == gq) ? acc1[0] : 0.f) + ((j1 == gq) ? acc1[1] : 0.f);
        float pB = ((j0 == gq) ? acc0[2] : 0.f) + ((j1 == gq) ? acc0[3] : 0.f);
        pA += __shfl_xor_sync(0xffffffffu, pA, 1);
        pA += __shfl_xor_sync(0xffffffffu, pA, 2);
        pB += __shfl_xor_sync(0xffffffffu, pB, 1);
        pB += __shfl_xor_sync(0xffffffffu, pB, 2);

        float v = (mA + __logf(eA) - pA) + (mB + __logf(eB) - pB);
        v = (t4 == 0) ? v : 0.f;
#pragma unroll
        for (int o = 16; o > 0; o >>= 1)
            v += __shfl_down_sync(0xffffffffu, v, o);
        if (lid == 0) myres = (double)v / (384.0 * (double)T);
    }
    if (lid == 0) wres[w] = myres;
    __syncthreads();
    if (tid == 0) {
        double tot = 0.0;
#pragma unroll
        for (int q = 0; q < 8; q++) tot += wres[q];
        atomicAdd(&g_acc, tot);
    }
}

// ---------------------------------------------------------------------------
// Chunked temporal kernel: block = (l, b, chunk of <=256 rows).
#define NS 96
#define NSP 97
#define NTH 256
__global__ void __launch_bounds__(NTH)
k_temp(const float* __restrict__ z1, const float* __restrict__ z2,
       float* __restrict__ out) {
    // decode block -> (l, b, chunk)
    int bid = blockIdx.x;
    int l = 0;
    for (;;) {
        int cnt = 16 * chunksOf(l);
        if (bid < cnt) break;
        bid -= cnt; ++l;
    }
    int nch = chunksOf(l);
    int b = bid / nch;
    int chunk = bid % nch;
    int T = TTOP >> l;
    int lb = l * 16 + b;
    const float* zb = lvl_base(l, b, z1, z2);
    int base = rowOff(l) * 16 + b * T;
    int tid = threadIdx.x;
    int sub = tid & 7, grp = tid >> 3;              // 8 threads per row, 32 rows
    int lane = tid & 31;

    __shared__ float s_pool[64 * NSP];              // finisher staging
    __shared__ float s_dg[2048];
    __shared__ unsigned short s_lst[2048];
    __shared__ float smax[NTH];
    __shared__ double sd[NTH];
    __shared__ int s_cnt;
    __shared__ int s_last;

    // ---- phase 1 on this chunk: coalesced, uniform trip count
    int r0 = chunk * 256;
    int r1 = min(r0 + 256, T);
    int rows = r1 - r0;
    float cs[8] = {0.f, 0.f, 0.f, 0.f, 0.f, 0.f, 0.f, 0.f};
    float mx = 0.f, nrmp = 0.f;
    int nIter = (rows + 31) >> 5;
    for (int it = 0; it < nIter; it++) {
        int x = r0 + it * 32 + grp;
        bool act = (x < r1);
        float4 a = make_float4(0.f, 0.f, 0.f, 0.f);
        float4 c4v = a;
        if (act) {
            const float4* row = reinterpret_cast<const float4*>(zb + (size_t)x * CDIM);
            a = row[2 * sub];
            c4v = row[2 * sub + 1];
        }
        cs[0] += a.x;   cs[1] += a.y;   cs[2] += a.z;   cs[3] += a.w;
        cs[4] += c4v.x; cs[5] += c4v.y; cs[6] += c4v.z; cs[7] += c4v.w;
        float np = a.x * a.x + a.y * a.y + a.z * a.z + a.w * a.w +
                   c4v.x * c4v.x + c4v.y * c4v.y + c4v.z * c4v.z + c4v.w * c4v.w;
        np += __shfl_xor_sync(0xffffffffu, np, 1);
        np += __shfl_xor_sync(0xffffffffu, np, 2);
        np += __shfl_xor_sync(0xffffffffu, np, 4);
        if (act) {
            if (sub == 0) { g_norm[base + x] = np; nrmp += np; }
            mx = fmaxf(mx, np);
        }
    }
#pragma unroll
    for (int q = 0; q < 8; q++) {
        cs[q] += __shfl_xor_sync(0xffffffffu, cs[q], 8);
        cs[q] += __shfl_xor_sync(0xffffffffu, cs[q], 16);
    }
    if (lane < 8) {
#pragma unroll
        for (int q = 0; q < 8; q++)
            atomicAdd(&g_svec[lb * 64 + 8 * lane + q], cs[q]);
    }
    smax[tid] = mx;
    sd[tid] = (double)nrmp;
    __syncthreads();
    for (int s = NTH / 2; s > 0; s >>= 1) {
        if (tid < s) {
            smax[tid] = fmaxf(smax[tid], smax[tid + s]);
            sd[tid] += sd[tid + s];
        }
        __syncthreads();
    }
    if (tid == 0) {
        atomicMax(&g_mx[lb], __float_as_int(smax[0]));   // norms >= 0
        atomicAdd(&g_nrm[lb], sd[0]);
        __threadfence();
        int done = atomicAdd(&g_ctr2[lb], 1);
        s_last = (done == nch - 1);
        s_cnt = 0;
    }
    __syncthreads();
    if (!s_last) return;
    __threadfence();                                 // see other chunks' writes

    // ======================= FINISHER (last chunk block) ====================
    float M10 = 10.f * __int_as_float(g_mx[lb]);
    double nrmtot = g_nrm[lb];

    // S2 from column sums
    double s2 = 0.0;
    if (tid < 64) {
        float S = g_svec[lb * 64 + tid];
        s2 = (double)S * (double)S;
    }
    sd[tid] = s2;
    __syncthreads();
    for (int s = NTH / 2; s > 0; s >>= 1) {
        if (tid < s) sd[tid] += sd[tid + s];
        __syncthreads();
    }
    double S2 = sd[0];
    __syncthreads();

    // phase 2: candidate compaction from g_norm
    {
        float rhs = M10 - 60.f;
        float thr2 = rhs * rhs;
        for (int x = tid; x < T; x += NTH) {
            float nx = g_norm[base + x];
            bool skip = (rhs > 0.f) && (10.f * nx * M10 < thr2);
            if (!skip) {
                int p = atomicAdd(&s_cnt, 1);
                s_lst[p] = (unsigned short)x;
            }
        }
    }
    __syncthreads();
    int n = s_cnt;

    for (int i = tid; i < n; i += NTH) s_dg[i] = 0.f;
    __syncthreads();

    if (n >= 2) {
        // phase 3: stage candidate rows transposed
        int nst = (n < NS) ? n : NS;
        for (int e = tid; e < nst * 64; e += NTH) {
            int i = e >> 6, k = e & 63;
            s_pool[k * NSP + i] = zb[(size_t)s_lst[i] * CDIM + k];
        }
        __syncthreads();

        // phase 4: flattened candidate-pair loop
        int npairs = n * (n - 1) / 2;
        for (int p = tid; p < npairs; p += NTH) {
            int i = 0, rem = p;
            while (rem >= n - 1 - i) { rem -= n - 1 - i; i++; }
            int j = i + 1 + rem;
            float acc = 0.f;
            if (j < NS) {
#pragma unroll
                for (int k = 0; k < 64; k++)
                    acc += s_pool[k * NSP + i] * s_pool[k * NSP + j];
            } else {
                const float* pi = zb + (size_t)s_lst[i] * CDIM;
                const float* pj = zb + (size_t)s_lst[j] * CDIM;
#pragma unroll
                for (int k = 0; k < 64; k++) acc += pi[k] * pj[k];
            }
            float s = 10.f * acc - M10;
            if (s > -70.f) {
                int pos = (s_lst[i] < s_lst[j]) ? i : j;
                atomicAdd(&s_dg[pos], __expf(s));
            }
        }
        __syncthreads();
    }

    // phase 5: closed-form base + O(n) correction
    float vbase = M10 + logf(1e-5f);
    double sum = (double)vbase * ((double)T * (double)(T - 1) * 0.5);
    double corr = 0.0;
    for (int i = tid; i < n; i += NTH) {
        float dg = s_dg[i];
        if (dg != 0.f) {
            int x = s_lst[i];
            float vr = M10 + logf(dg + 1e-5f);
            corr += (double)(T - 1 - x) * ((double)vr - (double)vbase);
        }
    }
    sd[tid] = corr;
    __syncthreads();
    for (int s = NTH / 2; s > 0; s >>= 1) {
        if (tid < s) sd[tid] += sd[tid + s];
        __syncthreads();
    }
    if (tid == 0) {
        double Ssum = 5.0 * (S2 - nrmtot);
        double wgt = 1.0 / (192.0 * (double)T * (double)(T - 1));
        atomicAdd(&g_acc, wgt * (sum + sd[0] - Ssum));
        __threadfence();
        int done = atomicAdd(&g_ctr, 1);
        if (done == NLB - 1) out[0] = (float)g_acc;
    }
}

// ---------------------------------------------------------------------------
extern "C" void kernel_launch(void* const* d_in, const int* in_sizes, int n_in,
                              void* d_out, int out_size) {
    const float* z1 = (const float*)d_in[0];
    const float* z2 = (const float*)d_in[1];
    float* out = (float*)d_out;

    k_poolA<<<128, 256>>>(z1, z2);            // also zeroes accumulators
    {
        int n = 2 * 512 * 31;
        k_poolB<<<(n + 255) / 256, 256>>>();
    }
    k_inst<<<512, 256>>>(z1, z2);

    // blocks: sum over l of 16*chunksOf(l) = 16*(8+4+2+1*8) = 352
    k_temp<<<352, NTH>>>(z1, z2, out);
}